// round 1
// baseline (speedup 1.0000x reference)
#include <cuda_runtime.h>
#include <cstdint>

// Problem constants (fixed shapes)
#define BB 4
#define NN 2048
#define DM 1024
#define HH 16
#define DH 64
#define NPHYS 8
#define M_ROWS (BB * NN)          // 8192
#define QKV_COLS (3 * DM)         // 3072

// Scratch (static device allocations; no cudaMalloc allowed)
__device__ float g_qkv[(size_t)M_ROWS * QKV_COLS];  // [B*N, 3D]
__device__ float g_att[(size_t)M_ROWS * DM];        // [B*N, D] (heads concatenated)

// ---------------------------------------------------------------------------
// SGEMM NT: C[M,N] = A[M,K] * B[N,K]^T, all row-major.
// M%128==0, N%128==0, K%16==0. 256 threads, 128x128 tile, 8x8 per thread.
// ---------------------------------------------------------------------------
__global__ __launch_bounds__(256) void sgemm_nt(const float* __restrict__ A,
                                                const float* __restrict__ Bm,
                                                float* __restrict__ C,
                                                int M, int N, int K)
{
    __shared__ float As[16][132];   // transposed: As[k][m]
    __shared__ float Bs[16][132];   // transposed: Bs[k][n]

    const int tid = threadIdx.x;
    const int tx = tid & 15;        // 0..15 -> output col group
    const int ty = tid >> 4;        // 0..15 -> output row group
    const int rowBase = blockIdx.y * 128;
    const int colBase = blockIdx.x * 128;

    float acc[8][8];
#pragma unroll
    for (int i = 0; i < 8; i++)
#pragma unroll
        for (int j = 0; j < 8; j++) acc[i][j] = 0.f;

    for (int k0 = 0; k0 < K; k0 += 16) {
        // Load A tile (128x16) and B tile (128x16): 512 float4 each, 2 per thread.
#pragma unroll
        for (int l = 0; l < 2; l++) {
            int f = tid + l * 256;
            int r  = f >> 2;              // 0..127
            int c4 = (f & 3) << 2;        // 0,4,8,12
            float4 av = *(const float4*)(A + (size_t)(rowBase + r) * K + k0 + c4);
            As[c4 + 0][r] = av.x; As[c4 + 1][r] = av.y;
            As[c4 + 2][r] = av.z; As[c4 + 3][r] = av.w;
            float4 bv = *(const float4*)(Bm + (size_t)(colBase + r) * K + k0 + c4);
            Bs[c4 + 0][r] = bv.x; Bs[c4 + 1][r] = bv.y;
            Bs[c4 + 2][r] = bv.z; Bs[c4 + 3][r] = bv.w;
        }
        __syncthreads();

#pragma unroll
        for (int kk = 0; kk < 16; kk++) {
            float4 a0 = *(const float4*)&As[kk][ty * 8];
            float4 a1 = *(const float4*)&As[kk][ty * 8 + 4];
            float4 b0 = *(const float4*)&Bs[kk][tx * 8];
            float4 b1 = *(const float4*)&Bs[kk][tx * 8 + 4];
            float a[8] = {a0.x, a0.y, a0.z, a0.w, a1.x, a1.y, a1.z, a1.w};
            float b[8] = {b0.x, b0.y, b0.z, b0.w, b1.x, b1.y, b1.z, b1.w};
#pragma unroll
            for (int i = 0; i < 8; i++)
#pragma unroll
                for (int j = 0; j < 8; j++) acc[i][j] += a[i] * b[j];
        }
        __syncthreads();
    }

    // Epilogue: row-major store, float4 x2 per row
#pragma unroll
    for (int i = 0; i < 8; i++) {
        float* cp = C + (size_t)(rowBase + ty * 8 + i) * N + colBase + tx * 8;
        *(float4*)(cp)     = make_float4(acc[i][0], acc[i][1], acc[i][2], acc[i][3]);
        *(float4*)(cp + 4) = make_float4(acc[i][4], acc[i][5], acc[i][6], acc[i][7]);
    }
}

// ---------------------------------------------------------------------------
// Flash attention, fp32. One block = 64 query rows x one (b,h).
// qkv layout: [B*N, 3072] with q at col h*64, k at 1024+h*64, v at 2048+h*64.
// Online softmax, bias added (scaled by beta[h]) for h < NPHYS.
// out: [B*N, 1024] at col h*64.
// smem: Qs[k][r], Ks[k][c], Vs[m][d], Ps[r][m], each 64x68 floats.
// ---------------------------------------------------------------------------
#define FA_SMEM (4 * 64 * 68 * 4)

__global__ __launch_bounds__(256) void flash_attn(const float* __restrict__ qkv,
                                                  const float* __restrict__ bias,
                                                  const float* __restrict__ beta,
                                                  float* __restrict__ out)
{
    extern __shared__ float sm[];
    float* Qs = sm;                 // [64][68] transposed  Qs[k][r]
    float* Ks = Qs + 64 * 68;       // [64][68] transposed  Ks[k][c]
    float* Vs = Ks + 64 * 68;       // [64][68] natural     Vs[m][d]
    float* Ps = Vs + 64 * 68;       // [64][68] natural     Ps[r][m]

    const int tid = threadIdx.x;
    const int tx = tid & 15;        // col group (4 cols)
    const int ty = tid >> 4;        // row group (4 rows)
    const int bh = blockIdx.y;
    const int b = bh >> 4, h = bh & 15;
    const int q0 = blockIdx.x * 64;

    const float* qbase = qkv + ((size_t)b * NN + q0) * QKV_COLS + h * DH;
    const float* kbase = qkv + ((size_t)b * NN) * QKV_COLS + DM + h * DH;
    const float* vbase = qkv + ((size_t)b * NN) * QKV_COLS + 2 * DM + h * DH;

    // Load Q tile, store transposed: Qs[c][r]
    for (int f = tid; f < 64 * 16; f += 256) {
        int r = f >> 4;
        int c4 = (f & 15) << 2;
        float4 v = *(const float4*)(qbase + (size_t)r * QKV_COLS + c4);
        Qs[(c4 + 0) * 68 + r] = v.x; Qs[(c4 + 1) * 68 + r] = v.y;
        Qs[(c4 + 2) * 68 + r] = v.z; Qs[(c4 + 3) * 68 + r] = v.w;
    }

    float m_old[4], lsum[4], o[4][4];
#pragma unroll
    for (int i = 0; i < 4; i++) {
        m_old[i] = -1e30f; lsum[i] = 0.f;
#pragma unroll
        for (int j = 0; j < 4; j++) o[i][j] = 0.f;
    }
    const float betah = (h < NPHYS) ? beta[h] : 0.f;
    const float scale = 0.125f;  // 1/sqrt(64)
    __syncthreads();

    for (int j0 = 0; j0 < NN; j0 += 64) {
        // Load K (transposed) and V (natural)
        for (int f = tid; f < 64 * 16; f += 256) {
            int r = f >> 4;
            int c4 = (f & 15) << 2;
            float4 kv = *(const float4*)(kbase + (size_t)(j0 + r) * QKV_COLS + c4);
            Ks[(c4 + 0) * 68 + r] = kv.x; Ks[(c4 + 1) * 68 + r] = kv.y;
            Ks[(c4 + 2) * 68 + r] = kv.z; Ks[(c4 + 3) * 68 + r] = kv.w;
            float4 vv = *(const float4*)(vbase + (size_t)(j0 + r) * QKV_COLS + c4);
            *(float4*)&Vs[r * 68 + c4] = vv;
        }
        __syncthreads();

        // S = Q K^T  (4x4 fragment per thread)
        float s[4][4];
#pragma unroll
        for (int i = 0; i < 4; i++)
#pragma unroll
            for (int j = 0; j < 4; j++) s[i][j] = 0.f;

#pragma unroll 16
        for (int k = 0; k < 64; k++) {
            float4 qa = *(const float4*)&Qs[k * 68 + 4 * ty];
            float4 kb = *(const float4*)&Ks[k * 68 + 4 * tx];
            float qv[4] = {qa.x, qa.y, qa.z, qa.w};
            float kvv[4] = {kb.x, kb.y, kb.z, kb.w};
#pragma unroll
            for (int i = 0; i < 4; i++)
#pragma unroll
                for (int j = 0; j < 4; j++) s[i][j] += qv[i] * kvv[j];
        }

        // scale + bias
        if (h < NPHYS) {
#pragma unroll
            for (int i = 0; i < 4; i++) {
                const float* bp = bias + ((size_t)b * NN + q0 + 4 * ty + i) * NN + j0 + 4 * tx;
                float4 bv = *(const float4*)bp;
                s[i][0] = s[i][0] * scale + betah * bv.x;
                s[i][1] = s[i][1] * scale + betah * bv.y;
                s[i][2] = s[i][2] * scale + betah * bv.z;
                s[i][3] = s[i][3] * scale + betah * bv.w;
            }
        } else {
#pragma unroll
            for (int i = 0; i < 4; i++)
#pragma unroll
                for (int j = 0; j < 4; j++) s[i][j] *= scale;
        }

        // Online softmax: row max over 16 tx lanes (half-warp xor shuffle)
        float m_new[4], corr[4], rs[4];
#pragma unroll
        for (int i = 0; i < 4; i++) {
            float rm = fmaxf(fmaxf(s[i][0], s[i][1]), fmaxf(s[i][2], s[i][3]));
#pragma unroll
            for (int off = 1; off < 16; off <<= 1)
                rm = fmaxf(rm, __shfl_xor_sync(0xffffffffu, rm, off));
            m_new[i] = fmaxf(m_old[i], rm);
            corr[i] = __expf(m_old[i] - m_new[i]);
            float r = 0.f;
#pragma unroll
            for (int j = 0; j < 4; j++) {
                s[i][j] = __expf(s[i][j] - m_new[i]);
                r += s[i][j];
            }
#pragma unroll
            for (int off = 1; off < 16; off <<= 1)
                r += __shfl_xor_sync(0xffffffffu, r, off);
            rs[i] = r;
            lsum[i] = lsum[i] * corr[i] + rs[i];
#pragma unroll
            for (int j = 0; j < 4; j++) o[i][j] *= corr[i];
            m_old[i] = m_new[i];
        }

        // Store P naturally: Ps[r][m]
#pragma unroll
        for (int i = 0; i < 4; i++)
            *(float4*)&Ps[(4 * ty + i) * 68 + 4 * tx] =
                make_float4(s[i][0], s[i][1], s[i][2], s[i][3]);
        __syncthreads();

        // O += P * V
#pragma unroll 8
        for (int m = 0; m < 64; m++) {
            float4 vb = *(const float4*)&Vs[m * 68 + 4 * tx];
            float p0 = Ps[(4 * ty + 0) * 68 + m];
            float p1 = Ps[(4 * ty + 1) * 68 + m];
            float p2 = Ps[(4 * ty + 2) * 68 + m];
            float p3 = Ps[(4 * ty + 3) * 68 + m];
            o[0][0] += p0 * vb.x; o[0][1] += p0 * vb.y; o[0][2] += p0 * vb.z; o[0][3] += p0 * vb.w;
            o[1][0] += p1 * vb.x; o[1][1] += p1 * vb.y; o[1][2] += p1 * vb.z; o[1][3] += p1 * vb.w;
            o[2][0] += p2 * vb.x; o[2][1] += p2 * vb.y; o[2][2] += p2 * vb.z; o[2][3] += p2 * vb.w;
            o[3][0] += p3 * vb.x; o[3][1] += p3 * vb.y; o[3][2] += p3 * vb.z; o[3][3] += p3 * vb.w;
        }
        __syncthreads();  // before next tile overwrites Ks/Vs/Ps
    }

    // Normalize and store: out[(b*N + q0+row)*D + h*64 + col]
#pragma unroll
    for (int i = 0; i < 4; i++) {
        float inv = 1.f / lsum[i];
        float* op = out + ((size_t)b * NN + q0 + 4 * ty + i) * DM + h * DH + 4 * tx;
        *(float4*)op = make_float4(o[i][0] * inv, o[i][1] * inv, o[i][2] * inv, o[i][3] * inv);
    }
}

// ---------------------------------------------------------------------------
extern "C" void kernel_launch(void* const* d_in, const int* in_sizes, int n_in,
                              void* d_out, int out_size)
{
    const float* x     = (const float*)d_in[0];  // [B,N,D]
    const float* bias  = (const float*)d_in[1];  // [B,1,N,N]
    const float* Wqkv  = (const float*)d_in[2];  // [3D,D]
    const float* Wproj = (const float*)d_in[3];  // [D,D]
    const float* beta  = (const float*)d_in[4];  // [1,8,1,1]
    float* out = (float*)d_out;                  // [B,N,D]

    float *qkv_ptr, *att_ptr;
    cudaGetSymbolAddress((void**)&qkv_ptr, g_qkv);
    cudaGetSymbolAddress((void**)&att_ptr, g_att);

    // 1) QKV projection: [8192,1024] x [3072,1024]^T -> [8192,3072]
    sgemm_nt<<<dim3(QKV_COLS / 128, M_ROWS / 128), 256>>>(x, Wqkv, qkv_ptr,
                                                          M_ROWS, QKV_COLS, DM);

    // 2) Fused flash attention
    cudaFuncSetAttribute(flash_attn, cudaFuncAttributeMaxDynamicSharedMemorySize, FA_SMEM);
    flash_attn<<<dim3(NN / 64, BB * HH), 256, FA_SMEM>>>(qkv_ptr, bias, beta, att_ptr);

    // 3) Output projection: [8192,1024] x [1024,1024]^T -> [8192,1024]
    sgemm_nt<<<dim3(DM / 128, M_ROWS / 128), 256>>>(att_ptr, Wproj, out,
                                                    M_ROWS, DM, DM);
}

// round 3
// speedup vs baseline: 1.2874x; 1.2874x over previous
#include <cuda_runtime.h>
#include <cstdint>

// Problem constants (fixed shapes)
#define BB 4
#define NN 2048
#define DM 1024
#define HH 16
#define DH 64
#define NPHYS 8
#define M_ROWS (BB * NN)          // 8192
#define QKV_COLS (3 * DM)         // 3072

// Scratch (static device allocations; no cudaMalloc allowed)
__device__ float g_qkv[(size_t)M_ROWS * QKV_COLS];  // [B*N, 3D]
__device__ float g_att[(size_t)M_ROWS * DM];        // [B*N, D]

__device__ __forceinline__ uint32_t f2tf32(float x) {
    uint32_t r;
    asm("cvt.rna.tf32.f32 %0, %1;" : "=r"(r) : "f"(x));
    return r;
}

__device__ __forceinline__ void mma_tf32(float* c, const uint32_t* a, const uint32_t* b) {
    asm volatile(
        "mma.sync.aligned.m16n8k8.row.col.f32.tf32.tf32.f32 "
        "{%0,%1,%2,%3}, {%4,%5,%6,%7}, {%8,%9}, {%0,%1,%2,%3};"
        : "+f"(c[0]), "+f"(c[1]), "+f"(c[2]), "+f"(c[3])
        : "r"(a[0]), "r"(a[1]), "r"(a[2]), "r"(a[3]), "r"(b[0]), "r"(b[1]));
}

// ---------------------------------------------------------------------------
// TF32 mma.sync GEMM NT: C[M,N] = A[M,K] * B[N,K]^T (row-major, fp32 in/out).
// 128x128 CTA tile, 8 warps (2 row x 4 col), warp tile 64x32, k-chunk 16.
// smem stride 136 floats -> conflict-free fragment gathers.
// ---------------------------------------------------------------------------
__global__ __launch_bounds__(256, 2) void gemm_mma(const float* __restrict__ A,
                                                   const float* __restrict__ Bm,
                                                   float* __restrict__ C,
                                                   int M, int Nn, int K)
{
    __shared__ uint32_t As[16][136];   // As[k][m], tf32 bits
    __shared__ uint32_t Bs[16][136];   // Bs[k][n], tf32 bits

    const int tid = threadIdx.x;
    const int w = tid >> 5, lane = tid & 31;
    const int wr = w >> 2;             // 0..1  -> row group (64 rows)
    const int wc = w & 3;              // 0..3  -> col group (32 cols)
    const int g = lane >> 2;           // groupID 0..7
    const int tg = lane & 3;           // thread-in-group 0..3
    const int rowBase = blockIdx.y * 128;
    const int colBase = blockIdx.x * 128;
    const float* Ag = A + (size_t)rowBase * K;
    const float* Bg = Bm + (size_t)colBase * K;

    float c[4][4][4];                  // [mfrag][nfrag][reg]
#pragma unroll
    for (int i = 0; i < 4; i++)
#pragma unroll
        for (int j = 0; j < 4; j++)
#pragma unroll
            for (int r = 0; r < 4; r++) c[i][j][r] = 0.f;

    for (int k0 = 0; k0 < K; k0 += 16) {
        // Load 128x16 A and B tiles: 512 float4 each, 2 per thread per matrix.
#pragma unroll
        for (int l = 0; l < 2; l++) {
            int f = tid + l * 256;
            int row = f >> 2;              // 0..127
            int c4 = (f & 3) << 2;         // 0,4,8,12
            float4 av = *(const float4*)(Ag + (size_t)row * K + k0 + c4);
            As[c4 + 0][row] = f2tf32(av.x); As[c4 + 1][row] = f2tf32(av.y);
            As[c4 + 2][row] = f2tf32(av.z); As[c4 + 3][row] = f2tf32(av.w);
            float4 bv = *(const float4*)(Bg + (size_t)row * K + k0 + c4);
            Bs[c4 + 0][row] = f2tf32(bv.x); Bs[c4 + 1][row] = f2tf32(bv.y);
            Bs[c4 + 2][row] = f2tf32(bv.z); Bs[c4 + 3][row] = f2tf32(bv.w);
        }
        __syncthreads();

#pragma unroll
        for (int ks = 0; ks < 2; ks++) {
            const int kb = ks * 8;
            uint32_t a[4][4], b[4][2];
#pragma unroll
            for (int i = 0; i < 4; i++) {
                const int m = wr * 64 + i * 16 + g;
                a[i][0] = As[kb + tg][m];
                a[i][1] = As[kb + tg][m + 8];
                a[i][2] = As[kb + tg + 4][m];
                a[i][3] = As[kb + tg + 4][m + 8];
            }
#pragma unroll
            for (int j = 0; j < 4; j++) {
                const int n = wc * 32 + j * 8 + g;
                b[j][0] = Bs[kb + tg][n];
                b[j][1] = Bs[kb + tg + 4][n];
            }
#pragma unroll
            for (int i = 0; i < 4; i++)
#pragma unroll
                for (int j = 0; j < 4; j++)
                    mma_tf32(c[i][j], a[i], b[j]);
        }
        __syncthreads();
    }

    // Epilogue: c[i][j] -> rows rowBase+wr*64+i*16+g (+8), cols colBase+wc*32+j*8+2*tg (+1)
#pragma unroll
    for (int i = 0; i < 4; i++) {
        const int r0 = rowBase + wr * 64 + i * 16 + g;
#pragma unroll
        for (int j = 0; j < 4; j++) {
            const int cl = colBase + wc * 32 + j * 8 + 2 * tg;
            *(float2*)(C + (size_t)r0 * Nn + cl)       = make_float2(c[i][j][0], c[i][j][1]);
            *(float2*)(C + (size_t)(r0 + 8) * Nn + cl) = make_float2(c[i][j][2], c[i][j][3]);
        }
    }
}

// ---------------------------------------------------------------------------
// Flash attention, fp32 (unchanged from R1).
// ---------------------------------------------------------------------------
#define FA_SMEM (4 * 64 * 68 * 4)

__global__ __launch_bounds__(256) void flash_attn(const float* __restrict__ qkv,
                                                  const float* __restrict__ bias,
                                                  const float* __restrict__ beta,
                                                  float* __restrict__ out)
{
    extern __shared__ float sm[];
    float* Qs = sm;
    float* Ks = Qs + 64 * 68;
    float* Vs = Ks + 64 * 68;
    float* Ps = Vs + 64 * 68;

    const int tid = threadIdx.x;
    const int tx = tid & 15;
    const int ty = tid >> 4;
    const int bh = blockIdx.y;
    const int b = bh >> 4, h = bh & 15;
    const int q0 = blockIdx.x * 64;

    const float* qbase = qkv + ((size_t)b * NN + q0) * QKV_COLS + h * DH;
    const float* kbase = qkv + ((size_t)b * NN) * QKV_COLS + DM + h * DH;
    const float* vbase = qkv + ((size_t)b * NN) * QKV_COLS + 2 * DM + h * DH;

    for (int f = tid; f < 64 * 16; f += 256) {
        int r = f >> 4;
        int c4 = (f & 15) << 2;
        float4 v = *(const float4*)(qbase + (size_t)r * QKV_COLS + c4);
        Qs[(c4 + 0) * 68 + r] = v.x; Qs[(c4 + 1) * 68 + r] = v.y;
        Qs[(c4 + 2) * 68 + r] = v.z; Qs[(c4 + 3) * 68 + r] = v.w;
    }

    float m_old[4], lsum[4], o[4][4];
#pragma unroll
    for (int i = 0; i < 4; i++) {
        m_old[i] = -1e30f; lsum[i] = 0.f;
#pragma unroll
        for (int j = 0; j < 4; j++) o[i][j] = 0.f;
    }
    const float betah = (h < NPHYS) ? beta[h] : 0.f;
    const float scale = 0.125f;
    __syncthreads();

    for (int j0 = 0; j0 < NN; j0 += 64) {
        for (int f = tid; f < 64 * 16; f += 256) {
            int r = f >> 4;
            int c4 = (f & 15) << 2;
            float4 kv = *(const float4*)(kbase + (size_t)(j0 + r) * QKV_COLS + c4);
            Ks[(c4 + 0) * 68 + r] = kv.x; Ks[(c4 + 1) * 68 + r] = kv.y;
            Ks[(c4 + 2) * 68 + r] = kv.z; Ks[(c4 + 3) * 68 + r] = kv.w;
            float4 vv = *(const float4*)(vbase + (size_t)(j0 + r) * QKV_COLS + c4);
            *(float4*)&Vs[r * 68 + c4] = vv;
        }
        __syncthreads();

        float s[4][4];
#pragma unroll
        for (int i = 0; i < 4; i++)
#pragma unroll
            for (int j = 0; j < 4; j++) s[i][j] = 0.f;

#pragma unroll 16
        for (int k = 0; k < 64; k++) {
            float4 qa = *(const float4*)&Qs[k * 68 + 4 * ty];
            float4 kb = *(const float4*)&Ks[k * 68 + 4 * tx];
            float qv[4] = {qa.x, qa.y, qa.z, qa.w};
            float kvv[4] = {kb.x, kb.y, kb.z, kb.w};
#pragma unroll
            for (int i = 0; i < 4; i++)
#pragma unroll
                for (int j = 0; j < 4; j++) s[i][j] += qv[i] * kvv[j];
        }

        if (h < NPHYS) {
#pragma unroll
            for (int i = 0; i < 4; i++) {
                const float* bp = bias + ((size_t)b * NN + q0 + 4 * ty + i) * NN + j0 + 4 * tx;
                float4 bv = *(const float4*)bp;
                s[i][0] = s[i][0] * scale + betah * bv.x;
                s[i][1] = s[i][1] * scale + betah * bv.y;
                s[i][2] = s[i][2] * scale + betah * bv.z;
                s[i][3] = s[i][3] * scale + betah * bv.w;
            }
        } else {
#pragma unroll
            for (int i = 0; i < 4; i++)
#pragma unroll
                for (int j = 0; j < 4; j++) s[i][j] *= scale;
        }

        float m_new[4], corr[4], rs[4];
#pragma unroll
        for (int i = 0; i < 4; i++) {
            float rm = fmaxf(fmaxf(s[i][0], s[i][1]), fmaxf(s[i][2], s[i][3]));
#pragma unroll
            for (int off = 1; off < 16; off <<= 1)
                rm = fmaxf(rm, __shfl_xor_sync(0xffffffffu, rm, off));
            m_new[i] = fmaxf(m_old[i], rm);
            corr[i] = __expf(m_old[i] - m_new[i]);
            float r = 0.f;
#pragma unroll
            for (int j = 0; j < 4; j++) {
                s[i][j] = __expf(s[i][j] - m_new[i]);
                r += s[i][j];
            }
#pragma unroll
            for (int off = 1; off < 16; off <<= 1)
                r += __shfl_xor_sync(0xffffffffu, r, off);
            rs[i] = r;
            lsum[i] = lsum[i] * corr[i] + rs[i];
#pragma unroll
            for (int j = 0; j < 4; j++) o[i][j] *= corr[i];
            m_old[i] = m_new[i];
        }

#pragma unroll
        for (int i = 0; i < 4; i++)
            *(float4*)&Ps[(4 * ty + i) * 68 + 4 * tx] =
                make_float4(s[i][0], s[i][1], s[i][2], s[i][3]);
        __syncthreads();

#pragma unroll 8
        for (int m = 0; m < 64; m++) {
            float4 vb = *(const float4*)&Vs[m * 68 + 4 * tx];
            float p0 = Ps[(4 * ty + 0) * 68 + m];
            float p1 = Ps[(4 * ty + 1) * 68 + m];
            float p2 = Ps[(4 * ty + 2) * 68 + m];
            float p3 = Ps[(4 * ty + 3) * 68 + m];
            o[0][0] += p0 * vb.x; o[0][1] += p0 * vb.y; o[0][2] += p0 * vb.z; o[0][3] += p0 * vb.w;
            o[1][0] += p1 * vb.x; o[1][1] += p1 * vb.y; o[1][2] += p1 * vb.z; o[1][3] += p1 * vb.w;
            o[2][0] += p2 * vb.x; o[2][1] += p2 * vb.y; o[2][2] += p2 * vb.z; o[2][3] += p2 * vb.w;
            o[3][0] += p3 * vb.x; o[3][1] += p3 * vb.y; o[3][2] += p3 * vb.z; o[3][3] += p3 * vb.w;
        }
        __syncthreads();
    }

#pragma unroll
    for (int i = 0; i < 4; i++) {
        float inv = 1.f / lsum[i];
        float* op = out + ((size_t)b * NN + q0 + 4 * ty + i) * DM + h * DH + 4 * tx;
        *(float4*)op = make_float4(o[i][0] * inv, o[i][1] * inv, o[i][2] * inv, o[i][3] * inv);
    }
}

// ---------------------------------------------------------------------------
extern "C" void kernel_launch(void* const* d_in, const int* in_sizes, int n_in,
                              void* d_out, int out_size)
{
    const float* x     = (const float*)d_in[0];
    const float* bias  = (const float*)d_in[1];
    const float* Wqkv  = (const float*)d_in[2];
    const float* Wproj = (const float*)d_in[3];
    const float* beta  = (const float*)d_in[4];
    float* out = (float*)d_out;

    float *qkv_ptr, *att_ptr;
    cudaGetSymbolAddress((void**)&qkv_ptr, g_qkv);
    cudaGetSymbolAddress((void**)&att_ptr, g_att);

    static bool attr_set = false;
    if (!attr_set) {
        cudaFuncSetAttribute(flash_attn, cudaFuncAttributeMaxDynamicSharedMemorySize, FA_SMEM);
        attr_set = true;
    }

    // 1) QKV projection: [8192,1024] x [3072,1024]^T -> [8192,3072]  (tf32 mma.sync)
    gemm_mma<<<dim3(QKV_COLS / 128, M_ROWS / 128), 256>>>(x, Wqkv, qkv_ptr,
                                                          M_ROWS, QKV_COLS, DM);

    // 2) Fused flash attention (fp32)
    flash_attn<<<dim3(NN / 64, BB * HH), 256, FA_SMEM>>>(qkv_ptr, bias, beta, att_ptr);

    // 3) Output projection: [8192,1024] x [1024,1024]^T -> [8192,1024]  (tf32 mma.sync)
    gemm_mma<<<dim3(DM / 128, M_ROWS / 128), 256>>>(att_ptr, Wproj, out,
                                                    M_ROWS, DM, DM);
}

// round 4
// speedup vs baseline: 1.8071x; 1.4036x over previous
#include <cuda_runtime.h>
#include <cstdint>

// Problem constants (fixed shapes)
#define BB 4
#define NN 2048
#define DM 1024
#define HH 16
#define DH 64
#define NPHYS 8
#define M_ROWS (BB * NN)          // 8192
#define QKV_COLS (3 * DM)         // 3072

__device__ float g_qkv[(size_t)M_ROWS * QKV_COLS];  // [B*N, 3D]
__device__ float g_att[(size_t)M_ROWS * DM];        // [B*N, D]

__device__ __forceinline__ uint32_t f2tf32(float x) {
    uint32_t r;
    asm("cvt.rna.tf32.f32 %0, %1;" : "=r"(r) : "f"(x));
    return r;
}

__device__ __forceinline__ void mma_tf32(float* c, const uint32_t* a, const uint32_t* b) {
    asm volatile(
        "mma.sync.aligned.m16n8k8.row.col.f32.tf32.tf32.f32 "
        "{%0,%1,%2,%3}, {%4,%5,%6,%7}, {%8,%9}, {%0,%1,%2,%3};"
        : "+f"(c[0]), "+f"(c[1]), "+f"(c[2]), "+f"(c[3])
        : "r"(a[0]), "r"(a[1]), "r"(a[2]), "r"(a[3]), "r"(b[0]), "r"(b[1]));
}

// ---------------------------------------------------------------------------
// TF32 mma.sync GEMM NT (unchanged from R3, validated).
// ---------------------------------------------------------------------------
__global__ __launch_bounds__(256, 2) void gemm_mma(const float* __restrict__ A,
                                                   const float* __restrict__ Bm,
                                                   float* __restrict__ C,
                                                   int M, int Nn, int K)
{
    __shared__ uint32_t As[16][136];
    __shared__ uint32_t Bs[16][136];

    const int tid = threadIdx.x;
    const int w = tid >> 5, lane = tid & 31;
    const int wr = w >> 2;
    const int wc = w & 3;
    const int g = lane >> 2;
    const int tg = lane & 3;
    const int rowBase = blockIdx.y * 128;
    const int colBase = blockIdx.x * 128;
    const float* Ag = A + (size_t)rowBase * K;
    const float* Bg = Bm + (size_t)colBase * K;

    float c[4][4][4];
#pragma unroll
    for (int i = 0; i < 4; i++)
#pragma unroll
        for (int j = 0; j < 4; j++)
#pragma unroll
            for (int r = 0; r < 4; r++) c[i][j][r] = 0.f;

    for (int k0 = 0; k0 < K; k0 += 16) {
#pragma unroll
        for (int l = 0; l < 2; l++) {
            int f = tid + l * 256;
            int row = f >> 2;
            int c4 = (f & 3) << 2;
            float4 av = *(const float4*)(Ag + (size_t)row * K + k0 + c4);
            As[c4 + 0][row] = f2tf32(av.x); As[c4 + 1][row] = f2tf32(av.y);
            As[c4 + 2][row] = f2tf32(av.z); As[c4 + 3][row] = f2tf32(av.w);
            float4 bv = *(const float4*)(Bg + (size_t)row * K + k0 + c4);
            Bs[c4 + 0][row] = f2tf32(bv.x); Bs[c4 + 1][row] = f2tf32(bv.y);
            Bs[c4 + 2][row] = f2tf32(bv.z); Bs[c4 + 3][row] = f2tf32(bv.w);
        }
        __syncthreads();

#pragma unroll
        for (int ks = 0; ks < 2; ks++) {
            const int kb = ks * 8;
            uint32_t a[4][4], b[4][2];
#pragma unroll
            for (int i = 0; i < 4; i++) {
                const int m = wr * 64 + i * 16 + g;
                a[i][0] = As[kb + tg][m];
                a[i][1] = As[kb + tg][m + 8];
                a[i][2] = As[kb + tg + 4][m];
                a[i][3] = As[kb + tg + 4][m + 8];
            }
#pragma unroll
            for (int j = 0; j < 4; j++) {
                const int n = wc * 32 + j * 8 + g;
                b[j][0] = Bs[kb + tg][n];
                b[j][1] = Bs[kb + tg + 4][n];
            }
#pragma unroll
            for (int i = 0; i < 4; i++)
#pragma unroll
                for (int j = 0; j < 4; j++)
                    mma_tf32(c[i][j], a[i], b[j]);
        }
        __syncthreads();
    }

#pragma unroll
    for (int i = 0; i < 4; i++) {
        const int r0 = rowBase + wr * 64 + i * 16 + g;
#pragma unroll
        for (int j = 0; j < 4; j++) {
            const int cl = colBase + wc * 32 + j * 8 + 2 * tg;
            *(float2*)(C + (size_t)r0 * Nn + cl)       = make_float2(c[i][j][0], c[i][j][1]);
            *(float2*)(C + (size_t)(r0 + 8) * Nn + cl) = make_float2(c[i][j][2], c[i][j][3]);
        }
    }
}

// ---------------------------------------------------------------------------
// Tensorized flash attention (tf32 mma.sync), 3-term compensated PV.
// Block: 128 q-rows x one (b,h). 8 warps; warp w owns q-rows [16w,16w+16).
// smem: Ks[64][72] (swizzled tf32 K), Vh/Vl[64][72] (tf32 V hi/lo),
//       Ps[8][16][68] (per-warp P staging). Q pre-scaled, in registers.
// ---------------------------------------------------------------------------
#define KS_W 72
#define PS_W 68
#define FA2_WORDS (3 * 64 * KS_W + 8 * 16 * PS_W)
#define FA2_SMEM (FA2_WORDS * 4)

__global__ __launch_bounds__(256, 2) void flash_mma(const float* __restrict__ qkv,
                                                    const float* __restrict__ bias,
                                                    const float* __restrict__ beta,
                                                    float* __restrict__ out)
{
    extern __shared__ uint32_t sm2[];
    uint32_t* Ks = sm2;                    // [64][72]
    uint32_t* Vh = sm2 + 64 * KS_W;        // [64][72]
    uint32_t* Vl = sm2 + 2 * 64 * KS_W;    // [64][72]
    uint32_t* Ps = sm2 + 3 * 64 * KS_W;    // [8][16][68]

    const int tid = threadIdx.x;
    const int w = tid >> 5, lane = tid & 31;
    const int g = lane >> 2, tg = lane & 3;
    const int b = blockIdx.y >> 4, h = blockIdx.y & 15;
    const int q0 = blockIdx.x * 128;

    const float* qbase = qkv + ((size_t)b * NN + q0) * QKV_COLS + h * DH;
    const float* kbase = qkv + ((size_t)b * NN) * QKV_COLS + DM + h * DH;
    const float* vbase = qkv + ((size_t)b * NN) * QKV_COLS + 2 * DM + h * DH;

    // ---- Stage Q (x 1/8, tf32, swizzled) into smem, then into registers ----
    {
        uint32_t* Qst = sm2;               // [128][72], overlays Ks+Vh
        for (int f = tid; f < 128 * 16; f += 256) {
            int row = f >> 4;
            int c4 = (f & 15) << 2;
            float4 v = *(const float4*)(qbase + (size_t)row * QKV_COLS + c4);
            int swz = ((row >> 2) & 1) << 2;
            uint4 t;
            t.x = f2tf32(v.x * 0.125f); t.y = f2tf32(v.y * 0.125f);
            t.z = f2tf32(v.z * 0.125f); t.w = f2tf32(v.w * 0.125f);
            *(uint4*)&Qst[row * KS_W + (c4 ^ swz)] = t;
        }
        __syncthreads();
    }
    const int qsw = ((g >> 2) & 1) << 2;   // swizzle const for this thread's rows/keys
    uint32_t q[8][4];
    {
        const uint32_t* Qst = sm2;
        const int r0 = w * 16 + g;
#pragma unroll
        for (int kb8 = 0; kb8 < 8; kb8++) {
            const int k0c = kb8 * 8;
            q[kb8][0] = Qst[r0 * KS_W + ((k0c + tg) ^ qsw)];
            q[kb8][1] = Qst[(r0 + 8) * KS_W + ((k0c + tg) ^ qsw)];
            q[kb8][2] = Qst[r0 * KS_W + ((k0c + tg + 4) ^ qsw)];
            q[kb8][3] = Qst[(r0 + 8) * KS_W + ((k0c + tg + 4) ^ qsw)];
        }
        __syncthreads();
    }

    float o[8][4];
#pragma unroll
    for (int j = 0; j < 8; j++)
#pragma unroll
        for (int r = 0; r < 4; r++) o[j][r] = 0.f;
    float m0 = -1e30f, m1 = -1e30f, l0 = 0.f, l1 = 0.f;
    const float betah = (h < NPHYS) ? beta[h] : 0.f;
    uint32_t* Pw = Ps + w * 16 * PS_W;

    for (int t32 = 0; t32 < 32; t32++) {
        const int j0 = t32 * 64;
        // ---- Load K (swizzled tf32) and V (hi/lo tf32) ----
#pragma unroll
        for (int l = 0; l < 4; l++) {
            int f = tid + l * 256;
            int row = f >> 4;
            int c4 = (f & 15) << 2;
            int swz = ((row >> 2) & 1) << 2;
            float4 kv = *(const float4*)(kbase + (size_t)(j0 + row) * QKV_COLS + c4);
            uint4 kt;
            kt.x = f2tf32(kv.x); kt.y = f2tf32(kv.y);
            kt.z = f2tf32(kv.z); kt.w = f2tf32(kv.w);
            *(uint4*)&Ks[row * KS_W + (c4 ^ swz)] = kt;
            float4 vv = *(const float4*)(vbase + (size_t)(j0 + row) * QKV_COLS + c4);
            uint4 vhi, vlo;
            vhi.x = f2tf32(vv.x); vlo.x = f2tf32(vv.x - __uint_as_float(vhi.x));
            vhi.y = f2tf32(vv.y); vlo.y = f2tf32(vv.y - __uint_as_float(vhi.y));
            vhi.z = f2tf32(vv.z); vlo.z = f2tf32(vv.z - __uint_as_float(vhi.z));
            vhi.w = f2tf32(vv.w); vlo.w = f2tf32(vv.w - __uint_as_float(vhi.w));
            *(uint4*)&Vh[row * KS_W + c4] = vhi;
            *(uint4*)&Vl[row * KS_W + c4] = vlo;
        }
        __syncthreads();

        // ---- S = (Q/8) K^T ----
        float s[8][4];
#pragma unroll
        for (int j = 0; j < 8; j++)
#pragma unroll
            for (int r = 0; r < 4; r++) s[j][r] = 0.f;
#pragma unroll
        for (int jj = 0; jj < 8; jj++) {
            const int key = jj * 8 + g;
#pragma unroll
            for (int kb8 = 0; kb8 < 8; kb8++) {
                uint32_t bb[2];
                bb[0] = Ks[key * KS_W + ((kb8 * 8 + tg) ^ qsw)];
                bb[1] = Ks[key * KS_W + ((kb8 * 8 + tg + 4) ^ qsw)];
                mma_tf32(s[jj], q[kb8], bb);
            }
        }

        // ---- bias (first NPHYS heads) ----
        if (h < NPHYS) {
            const float* bp = bias + ((size_t)b * NN + q0 + w * 16 + g) * NN + j0;
#pragma unroll
            for (int jj = 0; jj < 8; jj++) {
                float2 b0 = __ldg((const float2*)(bp + jj * 8 + 2 * tg));
                float2 b1 = __ldg((const float2*)(bp + 8 * NN + jj * 8 + 2 * tg));
                s[jj][0] += betah * b0.x; s[jj][1] += betah * b0.y;
                s[jj][2] += betah * b1.x; s[jj][3] += betah * b1.y;
            }
        }

        // ---- online softmax (rows g and g+8 of this warp's 16) ----
        float rm0 = -1e30f, rm1 = -1e30f;
#pragma unroll
        for (int jj = 0; jj < 8; jj++) {
            rm0 = fmaxf(rm0, fmaxf(s[jj][0], s[jj][1]));
            rm1 = fmaxf(rm1, fmaxf(s[jj][2], s[jj][3]));
        }
        rm0 = fmaxf(rm0, __shfl_xor_sync(0xffffffffu, rm0, 1));
        rm0 = fmaxf(rm0, __shfl_xor_sync(0xffffffffu, rm0, 2));
        rm1 = fmaxf(rm1, __shfl_xor_sync(0xffffffffu, rm1, 1));
        rm1 = fmaxf(rm1, __shfl_xor_sync(0xffffffffu, rm1, 2));
        const float mn0 = fmaxf(m0, rm0), mn1 = fmaxf(m1, rm1);
        const float c0 = __expf(m0 - mn0), c1 = __expf(m1 - mn1);
        float sum0 = 0.f, sum1 = 0.f;
#pragma unroll
        for (int jj = 0; jj < 8; jj++) {
            s[jj][0] = __expf(s[jj][0] - mn0); sum0 += s[jj][0];
            s[jj][1] = __expf(s[jj][1] - mn0); sum0 += s[jj][1];
            s[jj][2] = __expf(s[jj][2] - mn1); sum1 += s[jj][2];
            s[jj][3] = __expf(s[jj][3] - mn1); sum1 += s[jj][3];
        }
        sum0 += __shfl_xor_sync(0xffffffffu, sum0, 1);
        sum0 += __shfl_xor_sync(0xffffffffu, sum0, 2);
        sum1 += __shfl_xor_sync(0xffffffffu, sum1, 1);
        sum1 += __shfl_xor_sync(0xffffffffu, sum1, 2);
        l0 = l0 * c0 + sum0; m0 = mn0;
        l1 = l1 * c1 + sum1; m1 = mn1;
#pragma unroll
        for (int jj = 0; jj < 8; jj++) {
            o[jj][0] *= c0; o[jj][1] *= c0;
            o[jj][2] *= c1; o[jj][3] *= c1;
        }

        // ---- PV pass 1: Phi x (Vhi + Vlo) ----
#pragma unroll
        for (int jj = 0; jj < 8; jj++) {
            uint2 hi0 = make_uint2(f2tf32(s[jj][0]), f2tf32(s[jj][1]));
            uint2 hi1 = make_uint2(f2tf32(s[jj][2]), f2tf32(s[jj][3]));
            *(uint2*)&Pw[g * PS_W + jj * 8 + 2 * tg] = hi0;
            *(uint2*)&Pw[(g + 8) * PS_W + jj * 8 + 2 * tg] = hi1;
        }
        __syncwarp();
#pragma unroll
        for (int kb8 = 0; kb8 < 8; kb8++) {
            const int kc = kb8 * 8;
            uint32_t a[4];
            a[0] = Pw[g * PS_W + kc + tg];
            a[1] = Pw[(g + 8) * PS_W + kc + tg];
            a[2] = Pw[g * PS_W + kc + tg + 4];
            a[3] = Pw[(g + 8) * PS_W + kc + tg + 4];
#pragma unroll
            for (int jj = 0; jj < 8; jj++) {
                const int n = jj * 8 + g;
                uint32_t bh[2], bl[2];
                bh[0] = Vh[(kc + tg) * KS_W + n];
                bh[1] = Vh[(kc + tg + 4) * KS_W + n];
                bl[0] = Vl[(kc + tg) * KS_W + n];
                bl[1] = Vl[(kc + tg + 4) * KS_W + n];
                mma_tf32(o[jj], a, bh);
                mma_tf32(o[jj], a, bl);
            }
        }
        __syncwarp();

        // ---- PV pass 2: Plo x Vhi ----
#pragma unroll
        for (int jj = 0; jj < 8; jj++) {
            uint2 lo0, lo1;
            lo0.x = f2tf32(s[jj][0] - __uint_as_float(f2tf32(s[jj][0])));
            lo0.y = f2tf32(s[jj][1] - __uint_as_float(f2tf32(s[jj][1])));
            lo1.x = f2tf32(s[jj][2] - __uint_as_float(f2tf32(s[jj][2])));
            lo1.y = f2tf32(s[jj][3] - __uint_as_float(f2tf32(s[jj][3])));
            *(uint2*)&Pw[g * PS_W + jj * 8 + 2 * tg] = lo0;
            *(uint2*)&Pw[(g + 8) * PS_W + jj * 8 + 2 * tg] = lo1;
        }
        __syncwarp();
#pragma unroll
        for (int kb8 = 0; kb8 < 8; kb8++) {
            const int kc = kb8 * 8;
            uint32_t a[4];
            a[0] = Pw[g * PS_W + kc + tg];
            a[1] = Pw[(g + 8) * PS_W + kc + tg];
            a[2] = Pw[g * PS_W + kc + tg + 4];
            a[3] = Pw[(g + 8) * PS_W + kc + tg + 4];
#pragma unroll
            for (int jj = 0; jj < 8; jj++) {
                const int n = jj * 8 + g;
                uint32_t bh[2];
                bh[0] = Vh[(kc + tg) * KS_W + n];
                bh[1] = Vh[(kc + tg + 4) * KS_W + n];
                mma_tf32(o[jj], a, bh);
            }
        }
        __syncthreads();   // all reads of Ks/Vh/Vl done before next tile's loads
    }

    // ---- normalize + store ----
    const float inv0 = 1.f / l0, inv1 = 1.f / l1;
    float* op0 = out + ((size_t)b * NN + q0 + w * 16 + g) * DM + h * DH;
    float* op1 = op0 + (size_t)8 * DM;
#pragma unroll
    for (int jj = 0; jj < 8; jj++) {
        *(float2*)(op0 + jj * 8 + 2 * tg) = make_float2(o[jj][0] * inv0, o[jj][1] * inv0);
        *(float2*)(op1 + jj * 8 + 2 * tg) = make_float2(o[jj][2] * inv1, o[jj][3] * inv1);
    }
}

// ---------------------------------------------------------------------------
extern "C" void kernel_launch(void* const* d_in, const int* in_sizes, int n_in,
                              void* d_out, int out_size)
{
    const float* x     = (const float*)d_in[0];
    const float* bias  = (const float*)d_in[1];
    const float* Wqkv  = (const float*)d_in[2];
    const float* Wproj = (const float*)d_in[3];
    const float* beta  = (const float*)d_in[4];
    float* out = (float*)d_out;

    float *qkv_ptr, *att_ptr;
    cudaGetSymbolAddress((void**)&qkv_ptr, g_qkv);
    cudaGetSymbolAddress((void**)&att_ptr, g_att);

    static bool attr_set = false;
    if (!attr_set) {
        cudaFuncSetAttribute(flash_mma, cudaFuncAttributeMaxDynamicSharedMemorySize, FA2_SMEM);
        attr_set = true;
    }

    // 1) QKV projection (tf32 mma.sync)
    gemm_mma<<<dim3(QKV_COLS / 128, M_ROWS / 128), 256>>>(x, Wqkv, qkv_ptr,
                                                          M_ROWS, QKV_COLS, DM);

    // 2) Tensorized flash attention
    flash_mma<<<dim3(NN / 128, BB * HH), 256, FA2_SMEM>>>(qkv_ptr, bias, beta, att_ptr);

    // 3) Output projection (tf32 mma.sync)
    gemm_mma<<<dim3(DM / 128, M_ROWS / 128), 256>>>(att_ptr, Wproj, out,
                                                    M_ROWS, DM, DM);
}

// round 5
// speedup vs baseline: 2.7397x; 1.5161x over previous
#include <cuda_runtime.h>
#include <cstdint>

// Problem constants (fixed shapes)
#define BB 4
#define NN 2048
#define DM 1024
#define HH 16
#define DH 64
#define NPHYS 8
#define M_ROWS (BB * NN)          // 8192
#define QKV_COLS (3 * DM)         // 3072

__device__ float g_qkv[(size_t)M_ROWS * QKV_COLS];  // [B*N, 3D]
__device__ float g_att[(size_t)M_ROWS * DM];        // [B*N, D]

__device__ __forceinline__ uint32_t f2tf32(float x) {
    uint32_t r;
    asm("cvt.rna.tf32.f32 %0, %1;" : "=r"(r) : "f"(x));
    return r;
}

__device__ __forceinline__ void mma_tf32(float* c, const uint32_t* a, const uint32_t* b) {
    asm volatile(
        "mma.sync.aligned.m16n8k8.row.col.f32.tf32.tf32.f32 "
        "{%0,%1,%2,%3}, {%4,%5,%6,%7}, {%8,%9}, {%0,%1,%2,%3};"
        : "+f"(c[0]), "+f"(c[1]), "+f"(c[2]), "+f"(c[3])
        : "r"(a[0]), "r"(a[1]), "r"(a[2]), "r"(a[3]), "r"(b[0]), "r"(b[1]));
}

__device__ __forceinline__ void ldsm_x4(uint32_t& r0, uint32_t& r1, uint32_t& r2,
                                        uint32_t& r3, uint32_t addr) {
    asm volatile("ldmatrix.sync.aligned.m8n8.x4.shared.b16 {%0,%1,%2,%3}, [%4];"
                 : "=r"(r0), "=r"(r1), "=r"(r2), "=r"(r3) : "r"(addr));
}

// ---------------------------------------------------------------------------
// TF32 mma.sync GEMM NT: C[M,N] = A[M,K] * B[N,K]^T (row-major, fp32 in/out).
// 128x128 CTA tile, 8 warps (2x4), warp tile 64x32, k-chunk 16,
// double-buffered smem in [row][k] layout (stride 20), ldmatrix fragments.
// ---------------------------------------------------------------------------
#define GA_W 20

__global__ __launch_bounds__(256, 2) void gemm_mma(const float* __restrict__ A,
                                                   const float* __restrict__ Bm,
                                                   float* __restrict__ C,
                                                   int M, int Nn, int K)
{
    __shared__ uint32_t As[2][128 * GA_W];
    __shared__ uint32_t Bs[2][128 * GA_W];

    const int tid = threadIdx.x;
    const int w = tid >> 5, lane = tid & 31;
    const int wr = w >> 2;
    const int wc = w & 3;
    const int g = lane >> 2;
    const int tg = lane & 3;
    const int rowBase = blockIdx.y * 128;
    const int colBase = blockIdx.x * 128;
    const float* Ag = A + (size_t)rowBase * K;
    const float* Bg = Bm + (size_t)colBase * K;

    const uint32_t asB[2] = { (uint32_t)__cvta_generic_to_shared(As[0]),
                              (uint32_t)__cvta_generic_to_shared(As[1]) };
    const uint32_t bsB[2] = { (uint32_t)__cvta_generic_to_shared(Bs[0]),
                              (uint32_t)__cvta_generic_to_shared(Bs[1]) };

    // Per-thread ldmatrix address components
    const int aRow = lane & 15;                     // row-in-16 for A frags
    const int aCol = 4 * (lane >> 4);               // k sub-chunk for A frags
    const int bRow = (lane & 7) + 8 * ((lane >> 4) & 1);
    const int bCol = 4 * ((lane >> 3) & 1);

    // load/store row assignment (two float4 per matrix per thread)
    const int r0l = tid >> 2, c0l = (tid & 3) << 2;          // l=0
    const int r1l = (tid + 256) >> 2, c1l = ((tid + 256) & 3) << 2;  // l=1

    float c[4][4][4];
#pragma unroll
    for (int i = 0; i < 4; i++)
#pragma unroll
        for (int j = 0; j < 4; j++)
#pragma unroll
            for (int r = 0; r < 4; r++) c[i][j][r] = 0.f;

    auto cvt_store = [&](int buf, const float4& av0, const float4& av1,
                         const float4& bv0, const float4& bv1) {
        uint32_t* Ad = As[buf];
        uint32_t* Bd = Bs[buf];
        uint4 t;
        t.x = f2tf32(av0.x); t.y = f2tf32(av0.y); t.z = f2tf32(av0.z); t.w = f2tf32(av0.w);
        *(uint4*)&Ad[r0l * GA_W + c0l] = t;
        t.x = f2tf32(av1.x); t.y = f2tf32(av1.y); t.z = f2tf32(av1.z); t.w = f2tf32(av1.w);
        *(uint4*)&Ad[r1l * GA_W + c1l] = t;
        t.x = f2tf32(bv0.x); t.y = f2tf32(bv0.y); t.z = f2tf32(bv0.z); t.w = f2tf32(bv0.w);
        *(uint4*)&Bd[r0l * GA_W + c0l] = t;
        t.x = f2tf32(bv1.x); t.y = f2tf32(bv1.y); t.z = f2tf32(bv1.z); t.w = f2tf32(bv1.w);
        *(uint4*)&Bd[r1l * GA_W + c1l] = t;
    };

    // Preload chunk 0
    {
        float4 a0 = *(const float4*)(Ag + (size_t)r0l * K + c0l);
        float4 a1 = *(const float4*)(Ag + (size_t)r1l * K + c1l);
        float4 b0 = *(const float4*)(Bg + (size_t)r0l * K + c0l);
        float4 b1 = *(const float4*)(Bg + (size_t)r1l * K + c1l);
        cvt_store(0, a0, a1, b0, b1);
    }
    __syncthreads();

    const int nChunks = K >> 4;
    for (int ck = 0; ck < nChunks; ck++) {
        const int buf = ck & 1;
        float4 av0, av1, bv0, bv1;
        const bool more = (ck + 1 < nChunks);
        if (more) {
            const int k0 = (ck + 1) << 4;
            av0 = *(const float4*)(Ag + (size_t)r0l * K + k0 + c0l);
            av1 = *(const float4*)(Ag + (size_t)r1l * K + k0 + c1l);
            bv0 = *(const float4*)(Bg + (size_t)r0l * K + k0 + c0l);
            bv1 = *(const float4*)(Bg + (size_t)r1l * K + k0 + c1l);
        }

#pragma unroll
        for (int ks = 0; ks < 2; ks++) {
            const int kb = ks * 8;
            uint32_t a[4][4], b[4][2];
#pragma unroll
            for (int i = 0; i < 4; i++) {
                const int row = wr * 64 + i * 16 + aRow;
                ldsm_x4(a[i][0], a[i][1], a[i][2], a[i][3],
                        asB[buf] + (row * GA_W + kb + aCol) * 4);
            }
#pragma unroll
            for (int jp = 0; jp < 2; jp++) {
                const int row = wc * 32 + jp * 16 + bRow;
                ldsm_x4(b[2 * jp][0], b[2 * jp][1], b[2 * jp + 1][0], b[2 * jp + 1][1],
                        bsB[buf] + (row * GA_W + kb + bCol) * 4);
            }
#pragma unroll
            for (int i = 0; i < 4; i++)
#pragma unroll
                for (int j = 0; j < 4; j++)
                    mma_tf32(c[i][j], a[i], b[j]);
        }

        if (more) cvt_store(buf ^ 1, av0, av1, bv0, bv1);
        __syncthreads();
    }

#pragma unroll
    for (int i = 0; i < 4; i++) {
        const int r0 = rowBase + wr * 64 + i * 16 + g;
#pragma unroll
        for (int j = 0; j < 4; j++) {
            const int cl = colBase + wc * 32 + j * 8 + 2 * tg;
            *(float2*)(C + (size_t)r0 * Nn + cl)       = make_float2(c[i][j][0], c[i][j][1]);
            *(float2*)(C + (size_t)(r0 + 8) * Nn + cl) = make_float2(c[i][j][2], c[i][j][3]);
        }
    }
}

// ---------------------------------------------------------------------------
// Tensorized flash attention (tf32 mma.sync), Vhi+Vlo compensated PV,
// ldmatrix for S-loop B-frags and PV A-frags.
// ---------------------------------------------------------------------------
#define KS_W 72
#define PS_W 68
#define FA2_WORDS (3 * 64 * KS_W + 8 * 16 * PS_W)
#define FA2_SMEM (FA2_WORDS * 4)

__global__ __launch_bounds__(256, 2) void flash_mma(const float* __restrict__ qkv,
                                                    const float* __restrict__ bias,
                                                    const float* __restrict__ beta,
                                                    float* __restrict__ out)
{
    extern __shared__ uint32_t sm2[];
    uint32_t* Ks = sm2;                    // [64][72] swizzled tf32 K
    uint32_t* Vh = sm2 + 64 * KS_W;        // [64][72] tf32 V hi
    uint32_t* Vl = sm2 + 2 * 64 * KS_W;    // [64][72] tf32 V lo
    uint32_t* Ps = sm2 + 3 * 64 * KS_W;    // [8][16][68] P staging

    const int tid = threadIdx.x;
    const int w = tid >> 5, lane = tid & 31;
    const int g = lane >> 2, tg = lane & 3;
    const int b = blockIdx.y >> 4, h = blockIdx.y & 15;
    const int q0 = blockIdx.x * 128;

    const uint32_t ksBase = (uint32_t)__cvta_generic_to_shared(Ks);
    const uint32_t pwBase = (uint32_t)__cvta_generic_to_shared(Ps + w * 16 * PS_W);

    const float* qbase = qkv + ((size_t)b * NN + q0) * QKV_COLS + h * DH;
    const float* kbase = qkv + ((size_t)b * NN) * QKV_COLS + DM + h * DH;
    const float* vbase = qkv + ((size_t)b * NN) * QKV_COLS + 2 * DM + h * DH;

    // ---- Stage Q (x 1/8, tf32, swizzled) into smem, then into registers ----
    {
        uint32_t* Qst = sm2;               // [128][72], overlays Ks+Vh
        for (int f = tid; f < 128 * 16; f += 256) {
            int row = f >> 4;
            int c4 = (f & 15) << 2;
            float4 v = *(const float4*)(qbase + (size_t)row * QKV_COLS + c4);
            int swz = ((row >> 2) & 1) << 2;
            uint4 t;
            t.x = f2tf32(v.x * 0.125f); t.y = f2tf32(v.y * 0.125f);
            t.z = f2tf32(v.z * 0.125f); t.w = f2tf32(v.w * 0.125f);
            *(uint4*)&Qst[row * KS_W + (c4 ^ swz)] = t;
        }
        __syncthreads();
    }
    const int qsw = ((g >> 2) & 1) << 2;
    uint32_t q[8][4];
    {
        const uint32_t* Qst = sm2;
        const int r0 = w * 16 + g;
#pragma unroll
        for (int kb8 = 0; kb8 < 8; kb8++) {
            const int k0c = kb8 * 8;
            q[kb8][0] = Qst[r0 * KS_W + ((k0c + tg) ^ qsw)];
            q[kb8][1] = Qst[(r0 + 8) * KS_W + ((k0c + tg) ^ qsw)];
            q[kb8][2] = Qst[r0 * KS_W + ((k0c + tg + 4) ^ qsw)];
            q[kb8][3] = Qst[(r0 + 8) * KS_W + ((k0c + tg + 4) ^ qsw)];
        }
        __syncthreads();
    }

    float o[8][4];
#pragma unroll
    for (int j = 0; j < 8; j++)
#pragma unroll
        for (int r = 0; r < 4; r++) o[j][r] = 0.f;
    float m0 = -1e30f, m1 = -1e30f, l0 = 0.f, l1 = 0.f;
    const float betah = (h < NPHYS) ? beta[h] : 0.f;

    // ldmatrix address components (bytes offsets computed per use)
    const int sRowOff = lane & 7;                 // key-within-8 for S B-frags
    const int sColQ = 4 * (lane >> 3);            // 0,4,8,12 : k 16-chunk quarter
    const int swzl = (lane & 4);                  // row-swizzle for that key row
    const int pRow = lane & 15;
    const int pCol = 4 * (lane >> 4);

    for (int t32 = 0; t32 < 32; t32++) {
        const int j0 = t32 * 64;
        // ---- Load K (swizzled tf32) and V (hi/lo tf32) ----
#pragma unroll
        for (int l = 0; l < 4; l++) {
            int f = tid + l * 256;
            int row = f >> 4;
            int c4 = (f & 15) << 2;
            int swz = ((row >> 2) & 1) << 2;
            float4 kv = *(const float4*)(kbase + (size_t)(j0 + row) * QKV_COLS + c4);
            uint4 kt;
            kt.x = f2tf32(kv.x); kt.y = f2tf32(kv.y);
            kt.z = f2tf32(kv.z); kt.w = f2tf32(kv.w);
            *(uint4*)&Ks[row * KS_W + (c4 ^ swz)] = kt;
            float4 vv = *(const float4*)(vbase + (size_t)(j0 + row) * QKV_COLS + c4);
            uint4 vhi, vlo;
            vhi.x = f2tf32(vv.x); vlo.x = f2tf32(vv.x - __uint_as_float(vhi.x));
            vhi.y = f2tf32(vv.y); vlo.y = f2tf32(vv.y - __uint_as_float(vhi.y));
            vhi.z = f2tf32(vv.z); vlo.z = f2tf32(vv.z - __uint_as_float(vhi.z));
            vhi.w = f2tf32(vv.w); vlo.w = f2tf32(vv.w - __uint_as_float(vhi.w));
            *(uint4*)&Vh[row * KS_W + c4] = vhi;
            *(uint4*)&Vl[row * KS_W + c4] = vlo;
        }
        __syncthreads();

        // ---- S = (Q/8) K^T : B-frags via ldmatrix.x4 ----
        float s[8][4];
#pragma unroll
        for (int j = 0; j < 8; j++)
#pragma unroll
            for (int r = 0; r < 4; r++) s[j][r] = 0.f;
#pragma unroll
        for (int jj = 0; jj < 8; jj++) {
            const int krow = jj * 8 + sRowOff;
#pragma unroll
            for (int kq = 0; kq < 4; kq++) {
                uint32_t b0, b1, b2, b3;
                ldsm_x4(b0, b1, b2, b3,
                        ksBase + (krow * KS_W + ((kq * 16 + sColQ) ^ swzl)) * 4);
                uint32_t bb0[2] = {b0, b1}, bb1[2] = {b2, b3};
                mma_tf32(s[jj], q[2 * kq], bb0);
                mma_tf32(s[jj], q[2 * kq + 1], bb1);
            }
        }

        // ---- bias (first NPHYS heads) ----
        if (h < NPHYS) {
            const float* bp = bias + ((size_t)b * NN + q0 + w * 16 + g) * NN + j0;
#pragma unroll
            for (int jj = 0; jj < 8; jj++) {
                float2 b0 = __ldg((const float2*)(bp + jj * 8 + 2 * tg));
                float2 b1 = __ldg((const float2*)(bp + 8 * NN + jj * 8 + 2 * tg));
                s[jj][0] += betah * b0.x; s[jj][1] += betah * b0.y;
                s[jj][2] += betah * b1.x; s[jj][3] += betah * b1.y;
            }
        }

        // ---- online softmax ----
        float rm0 = -1e30f, rm1 = -1e30f;
#pragma unroll
        for (int jj = 0; jj < 8; jj++) {
            rm0 = fmaxf(rm0, fmaxf(s[jj][0], s[jj][1]));
            rm1 = fmaxf(rm1, fmaxf(s[jj][2], s[jj][3]));
        }
        rm0 = fmaxf(rm0, __shfl_xor_sync(0xffffffffu, rm0, 1));
        rm0 = fmaxf(rm0, __shfl_xor_sync(0xffffffffu, rm0, 2));
        rm1 = fmaxf(rm1, __shfl_xor_sync(0xffffffffu, rm1, 1));
        rm1 = fmaxf(rm1, __shfl_xor_sync(0xffffffffu, rm1, 2));
        const float mn0 = fmaxf(m0, rm0), mn1 = fmaxf(m1, rm1);
        const float c0 = __expf(m0 - mn0), c1 = __expf(m1 - mn1);
        float sum0 = 0.f, sum1 = 0.f;
#pragma unroll
        for (int jj = 0; jj < 8; jj++) {
            s[jj][0] = __expf(s[jj][0] - mn0); sum0 += s[jj][0];
            s[jj][1] = __expf(s[jj][1] - mn0); sum0 += s[jj][1];
            s[jj][2] = __expf(s[jj][2] - mn1); sum1 += s[jj][2];
            s[jj][3] = __expf(s[jj][3] - mn1); sum1 += s[jj][3];
        }
        sum0 += __shfl_xor_sync(0xffffffffu, sum0, 1);
        sum0 += __shfl_xor_sync(0xffffffffu, sum0, 2);
        sum1 += __shfl_xor_sync(0xffffffffu, sum1, 1);
        sum1 += __shfl_xor_sync(0xffffffffu, sum1, 2);
        l0 = l0 * c0 + sum0; m0 = mn0;
        l1 = l1 * c1 + sum1; m1 = mn1;
#pragma unroll
        for (int jj = 0; jj < 8; jj++) {
            o[jj][0] *= c0; o[jj][1] *= c0;
            o[jj][2] *= c1; o[jj][3] *= c1;
        }

        // ---- stage P (tf32), then PV: Phi x (Vhi + Vlo) ----
        {
            uint32_t* Pw = Ps + w * 16 * PS_W;
#pragma unroll
            for (int jj = 0; jj < 8; jj++) {
                uint2 hi0 = make_uint2(f2tf32(s[jj][0]), f2tf32(s[jj][1]));
                uint2 hi1 = make_uint2(f2tf32(s[jj][2]), f2tf32(s[jj][3]));
                *(uint2*)&Pw[g * PS_W + jj * 8 + 2 * tg] = hi0;
                *(uint2*)&Pw[(g + 8) * PS_W + jj * 8 + 2 * tg] = hi1;
            }
        }
        __syncwarp();
#pragma unroll
        for (int kb8 = 0; kb8 < 8; kb8++) {
            const int kc = kb8 * 8;
            uint32_t a[4];
            ldsm_x4(a[0], a[1], a[2], a[3],
                    pwBase + (pRow * PS_W + kc + pCol) * 4);
#pragma unroll
            for (int jj = 0; jj < 8; jj++) {
                const int n = jj * 8 + g;
                uint32_t bh[2], bl[2];
                bh[0] = Vh[(kc + tg) * KS_W + n];
                bh[1] = Vh[(kc + tg + 4) * KS_W + n];
                bl[0] = Vl[(kc + tg) * KS_W + n];
                bl[1] = Vl[(kc + tg + 4) * KS_W + n];
                mma_tf32(o[jj], a, bh);
                mma_tf32(o[jj], a, bl);
            }
        }
        __syncthreads();   // all reads of Ks/Vh/Vl/Ps done before next tile
    }

    // ---- normalize + store ----
    const float inv0 = 1.f / l0, inv1 = 1.f / l1;
    float* op0 = out + ((size_t)b * NN + q0 + w * 16 + g) * DM + h * DH;
    float* op1 = op0 + (size_t)8 * DM;
#pragma unroll
    for (int jj = 0; jj < 8; jj++) {
        *(float2*)(op0 + jj * 8 + 2 * tg) = make_float2(o[jj][0] * inv0, o[jj][1] * inv0);
        *(float2*)(op1 + jj * 8 + 2 * tg) = make_float2(o[jj][2] * inv1, o[jj][3] * inv1);
    }
}

// ---------------------------------------------------------------------------
extern "C" void kernel_launch(void* const* d_in, const int* in_sizes, int n_in,
                              void* d_out, int out_size)
{
    const float* x     = (const float*)d_in[0];
    const float* bias  = (const float*)d_in[1];
    const float* Wqkv  = (const float*)d_in[2];
    const float* Wproj = (const float*)d_in[3];
    const float* beta  = (const float*)d_in[4];
    float* out = (float*)d_out;

    float *qkv_ptr, *att_ptr;
    cudaGetSymbolAddress((void**)&qkv_ptr, g_qkv);
    cudaGetSymbolAddress((void**)&att_ptr, g_att);

    static bool attr_set = false;
    if (!attr_set) {
        cudaFuncSetAttribute(flash_mma, cudaFuncAttributeMaxDynamicSharedMemorySize, FA2_SMEM);
        attr_set = true;
    }

    // 1) QKV projection (tf32 mma.sync, double-buffered, ldmatrix)
    gemm_mma<<<dim3(QKV_COLS / 128, M_ROWS / 128), 256>>>(x, Wqkv, qkv_ptr,
                                                          M_ROWS, QKV_COLS, DM);

    // 2) Tensorized flash attention
    flash_mma<<<dim3(NN / 128, BB * HH), 256, FA2_SMEM>>>(qkv_ptr, bias, beta, att_ptr);

    // 3) Output projection (tf32 mma.sync)
    gemm_mma<<<dim3(DM / 128, M_ROWS / 128), 256>>>(att_ptr, Wproj, out,
                                                    M_ROWS, DM, DM);
}

// round 6
// speedup vs baseline: 3.0586x; 1.1164x over previous
#include <cuda_runtime.h>
#include <cstdint>

// Problem constants (fixed shapes)
#define BB 4
#define NN 2048
#define DM 1024
#define HH 16
#define DH 64
#define NPHYS 8
#define M_ROWS (BB * NN)          // 8192
#define QKV_COLS (3 * DM)         // 3072

__device__ float g_qkv[(size_t)M_ROWS * QKV_COLS];  // [B*N, 3D]
__device__ float g_att[(size_t)M_ROWS * DM];        // [B*N, D]

__device__ __forceinline__ uint32_t f2tf32(float x) {
    uint32_t r;
    asm("cvt.rna.tf32.f32 %0, %1;" : "=r"(r) : "f"(x));
    return r;
}

__device__ __forceinline__ void mma_tf32(float* c, const uint32_t* a, const uint32_t* b) {
    asm volatile(
        "mma.sync.aligned.m16n8k8.row.col.f32.tf32.tf32.f32 "
        "{%0,%1,%2,%3}, {%4,%5,%6,%7}, {%8,%9}, {%0,%1,%2,%3};"
        : "+f"(c[0]), "+f"(c[1]), "+f"(c[2]), "+f"(c[3])
        : "r"(a[0]), "r"(a[1]), "r"(a[2]), "r"(a[3]), "r"(b[0]), "r"(b[1]));
}

__device__ __forceinline__ void ldsm_x4(uint32_t& r0, uint32_t& r1, uint32_t& r2,
                                        uint32_t& r3, uint32_t addr) {
    asm volatile("ldmatrix.sync.aligned.m8n8.x4.shared.b16 {%0,%1,%2,%3}, [%4];"
                 : "=r"(r0), "=r"(r1), "=r"(r2), "=r"(r3) : "r"(addr));
}

// ---------------------------------------------------------------------------
// TF32 mma.sync GEMM NT (unchanged from R5, validated).
// ---------------------------------------------------------------------------
#define GA_W 20

__global__ __launch_bounds__(256, 2) void gemm_mma(const float* __restrict__ A,
                                                   const float* __restrict__ Bm,
                                                   float* __restrict__ C,
                                                   int M, int Nn, int K)
{
    __shared__ uint32_t As[2][128 * GA_W];
    __shared__ uint32_t Bs[2][128 * GA_W];

    const int tid = threadIdx.x;
    const int w = tid >> 5, lane = tid & 31;
    const int wr = w >> 2;
    const int wc = w & 3;
    const int g = lane >> 2;
    const int tg = lane & 3;
    const int rowBase = blockIdx.y * 128;
    const int colBase = blockIdx.x * 128;
    const float* Ag = A + (size_t)rowBase * K;
    const float* Bg = Bm + (size_t)colBase * K;

    const uint32_t asB[2] = { (uint32_t)__cvta_generic_to_shared(As[0]),
                              (uint32_t)__cvta_generic_to_shared(As[1]) };
    const uint32_t bsB[2] = { (uint32_t)__cvta_generic_to_shared(Bs[0]),
                              (uint32_t)__cvta_generic_to_shared(Bs[1]) };

    const int aRow = lane & 15;
    const int aCol = 4 * (lane >> 4);
    const int bRow = (lane & 7) + 8 * ((lane >> 4) & 1);
    const int bCol = 4 * ((lane >> 3) & 1);

    const int r0l = tid >> 2, c0l = (tid & 3) << 2;
    const int r1l = (tid + 256) >> 2, c1l = ((tid + 256) & 3) << 2;

    float c[4][4][4];
#pragma unroll
    for (int i = 0; i < 4; i++)
#pragma unroll
        for (int j = 0; j < 4; j++)
#pragma unroll
            for (int r = 0; r < 4; r++) c[i][j][r] = 0.f;

    auto cvt_store = [&](int buf, const float4& av0, const float4& av1,
                         const float4& bv0, const float4& bv1) {
        uint32_t* Ad = As[buf];
        uint32_t* Bd = Bs[buf];
        uint4 t;
        t.x = f2tf32(av0.x); t.y = f2tf32(av0.y); t.z = f2tf32(av0.z); t.w = f2tf32(av0.w);
        *(uint4*)&Ad[r0l * GA_W + c0l] = t;
        t.x = f2tf32(av1.x); t.y = f2tf32(av1.y); t.z = f2tf32(av1.z); t.w = f2tf32(av1.w);
        *(uint4*)&Ad[r1l * GA_W + c1l] = t;
        t.x = f2tf32(bv0.x); t.y = f2tf32(bv0.y); t.z = f2tf32(bv0.z); t.w = f2tf32(bv0.w);
        *(uint4*)&Bd[r0l * GA_W + c0l] = t;
        t.x = f2tf32(bv1.x); t.y = f2tf32(bv1.y); t.z = f2tf32(bv1.z); t.w = f2tf32(bv1.w);
        *(uint4*)&Bd[r1l * GA_W + c1l] = t;
    };

    {
        float4 a0 = *(const float4*)(Ag + (size_t)r0l * K + c0l);
        float4 a1 = *(const float4*)(Ag + (size_t)r1l * K + c1l);
        float4 b0 = *(const float4*)(Bg + (size_t)r0l * K + c0l);
        float4 b1 = *(const float4*)(Bg + (size_t)r1l * K + c1l);
        cvt_store(0, a0, a1, b0, b1);
    }
    __syncthreads();

    const int nChunks = K >> 4;
    for (int ck = 0; ck < nChunks; ck++) {
        const int buf = ck & 1;
        float4 av0, av1, bv0, bv1;
        const bool more = (ck + 1 < nChunks);
        if (more) {
            const int k0 = (ck + 1) << 4;
            av0 = *(const float4*)(Ag + (size_t)r0l * K + k0 + c0l);
            av1 = *(const float4*)(Ag + (size_t)r1l * K + k0 + c1l);
            bv0 = *(const float4*)(Bg + (size_t)r0l * K + k0 + c0l);
            bv1 = *(const float4*)(Bg + (size_t)r1l * K + k0 + c1l);
        }

#pragma unroll
        for (int ks = 0; ks < 2; ks++) {
            const int kb = ks * 8;
            uint32_t a[4][4], b[4][2];
#pragma unroll
            for (int i = 0; i < 4; i++) {
                const int row = wr * 64 + i * 16 + aRow;
                ldsm_x4(a[i][0], a[i][1], a[i][2], a[i][3],
                        asB[buf] + (row * GA_W + kb + aCol) * 4);
            }
#pragma unroll
            for (int jp = 0; jp < 2; jp++) {
                const int row = wc * 32 + jp * 16 + bRow;
                ldsm_x4(b[2 * jp][0], b[2 * jp][1], b[2 * jp + 1][0], b[2 * jp + 1][1],
                        bsB[buf] + (row * GA_W + kb + bCol) * 4);
            }
#pragma unroll
            for (int i = 0; i < 4; i++)
#pragma unroll
                for (int j = 0; j < 4; j++)
                    mma_tf32(c[i][j], a[i], b[j]);
        }

        if (more) cvt_store(buf ^ 1, av0, av1, bv0, bv1);
        __syncthreads();
    }

#pragma unroll
    for (int i = 0; i < 4; i++) {
        const int r0 = rowBase + wr * 64 + i * 16 + g;
#pragma unroll
        for (int j = 0; j < 4; j++) {
            const int cl = colBase + wc * 32 + j * 8 + 2 * tg;
            *(float2*)(C + (size_t)r0 * Nn + cl)       = make_float2(c[i][j][0], c[i][j][1]);
            *(float2*)(C + (size_t)(r0 + 8) * Nn + cl) = make_float2(c[i][j][2], c[i][j][3]);
        }
    }
}

// ---------------------------------------------------------------------------
// Tensorized flash attention (tf32 mma.sync), single-MMA PV (no Vlo pass).
// ---------------------------------------------------------------------------
#define KS_W 72
#define PS_W 68
#define FA2_WORDS (2 * 64 * KS_W + 8 * 16 * PS_W)
#define FA2_SMEM (FA2_WORDS * 4)

__global__ __launch_bounds__(256, 2) void flash_mma(const float* __restrict__ qkv,
                                                    const float* __restrict__ bias,
                                                    const float* __restrict__ beta,
                                                    float* __restrict__ out)
{
    extern __shared__ uint32_t sm2[];
    uint32_t* Ks = sm2;                    // [64][72] swizzled tf32 K
    uint32_t* Vs = sm2 + 64 * KS_W;        // [64][72] tf32 V
    uint32_t* Ps = sm2 + 2 * 64 * KS_W;    // [8][16][68] P staging

    const int tid = threadIdx.x;
    const int w = tid >> 5, lane = tid & 31;
    const int g = lane >> 2, tg = lane & 3;
    const int b = blockIdx.y >> 4, h = blockIdx.y & 15;
    const int q0 = blockIdx.x * 128;

    const uint32_t ksBase = (uint32_t)__cvta_generic_to_shared(Ks);
    const uint32_t pwBase = (uint32_t)__cvta_generic_to_shared(Ps + w * 16 * PS_W);

    const float* qbase = qkv + ((size_t)b * NN + q0) * QKV_COLS + h * DH;
    const float* kbase = qkv + ((size_t)b * NN) * QKV_COLS + DM + h * DH;
    const float* vbase = qkv + ((size_t)b * NN) * QKV_COLS + 2 * DM + h * DH;

    // ---- Stage Q (x 1/8, tf32, swizzled) into smem, then into registers ----
    {
        uint32_t* Qst = sm2;               // [128][72], overlays Ks+Vs
        for (int f = tid; f < 128 * 16; f += 256) {
            int row = f >> 4;
            int c4 = (f & 15) << 2;
            float4 v = *(const float4*)(qbase + (size_t)row * QKV_COLS + c4);
            int swz = ((row >> 2) & 1) << 2;
            uint4 t;
            t.x = f2tf32(v.x * 0.125f); t.y = f2tf32(v.y * 0.125f);
            t.z = f2tf32(v.z * 0.125f); t.w = f2tf32(v.w * 0.125f);
            *(uint4*)&Qst[row * KS_W + (c4 ^ swz)] = t;
        }
        __syncthreads();
    }
    const int qsw = ((g >> 2) & 1) << 2;
    uint32_t q[8][4];
    {
        const uint32_t* Qst = sm2;
        const int r0 = w * 16 + g;
#pragma unroll
        for (int kb8 = 0; kb8 < 8; kb8++) {
            const int k0c = kb8 * 8;
            q[kb8][0] = Qst[r0 * KS_W + ((k0c + tg) ^ qsw)];
            q[kb8][1] = Qst[(r0 + 8) * KS_W + ((k0c + tg) ^ qsw)];
            q[kb8][2] = Qst[r0 * KS_W + ((k0c + tg + 4) ^ qsw)];
            q[kb8][3] = Qst[(r0 + 8) * KS_W + ((k0c + tg + 4) ^ qsw)];
        }
        __syncthreads();
    }

    float o[8][4];
#pragma unroll
    for (int j = 0; j < 8; j++)
#pragma unroll
        for (int r = 0; r < 4; r++) o[j][r] = 0.f;
    float m0 = -1e30f, m1 = -1e30f, l0 = 0.f, l1 = 0.f;
    const float betah = (h < NPHYS) ? beta[h] : 0.f;

    const int sRowOff = lane & 7;
    const int sColQ = 4 * (lane >> 3);
    const int swzl = (lane & 4);
    const int pRow = lane & 15;
    const int pCol = 4 * (lane >> 4);

    for (int t32 = 0; t32 < 32; t32++) {
        const int j0 = t32 * 64;
        // ---- Load K (swizzled tf32) and V (tf32) ----
#pragma unroll
        for (int l = 0; l < 4; l++) {
            int f = tid + l * 256;
            int row = f >> 4;
            int c4 = (f & 15) << 2;
            int swz = ((row >> 2) & 1) << 2;
            float4 kv = *(const float4*)(kbase + (size_t)(j0 + row) * QKV_COLS + c4);
            uint4 kt;
            kt.x = f2tf32(kv.x); kt.y = f2tf32(kv.y);
            kt.z = f2tf32(kv.z); kt.w = f2tf32(kv.w);
            *(uint4*)&Ks[row * KS_W + (c4 ^ swz)] = kt;
            float4 vv = *(const float4*)(vbase + (size_t)(j0 + row) * QKV_COLS + c4);
            uint4 vt;
            vt.x = f2tf32(vv.x); vt.y = f2tf32(vv.y);
            vt.z = f2tf32(vv.z); vt.w = f2tf32(vv.w);
            *(uint4*)&Vs[row * KS_W + c4] = vt;
        }
        __syncthreads();

        // ---- S = (Q/8) K^T : B-frags via ldmatrix.x4 ----
        float s[8][4];
#pragma unroll
        for (int j = 0; j < 8; j++)
#pragma unroll
            for (int r = 0; r < 4; r++) s[j][r] = 0.f;
#pragma unroll
        for (int jj = 0; jj < 8; jj++) {
            const int krow = jj * 8 + sRowOff;
#pragma unroll
            for (int kq = 0; kq < 4; kq++) {
                uint32_t b0, b1, b2, b3;
                ldsm_x4(b0, b1, b2, b3,
                        ksBase + (krow * KS_W + ((kq * 16 + sColQ) ^ swzl)) * 4);
                uint32_t bb0[2] = {b0, b1}, bb1[2] = {b2, b3};
                mma_tf32(s[jj], q[2 * kq], bb0);
                mma_tf32(s[jj], q[2 * kq + 1], bb1);
            }
        }

        // ---- bias (first NPHYS heads) ----
        if (h < NPHYS) {
            const float* bp = bias + ((size_t)b * NN + q0 + w * 16 + g) * NN + j0;
#pragma unroll
            for (int jj = 0; jj < 8; jj++) {
                float2 b0 = __ldg((const float2*)(bp + jj * 8 + 2 * tg));
                float2 b1 = __ldg((const float2*)(bp + 8 * NN + jj * 8 + 2 * tg));
                s[jj][0] += betah * b0.x; s[jj][1] += betah * b0.y;
                s[jj][2] += betah * b1.x; s[jj][3] += betah * b1.y;
            }
        }

        // ---- online softmax ----
        float rm0 = -1e30f, rm1 = -1e30f;
#pragma unroll
        for (int jj = 0; jj < 8; jj++) {
            rm0 = fmaxf(rm0, fmaxf(s[jj][0], s[jj][1]));
            rm1 = fmaxf(rm1, fmaxf(s[jj][2], s[jj][3]));
        }
        rm0 = fmaxf(rm0, __shfl_xor_sync(0xffffffffu, rm0, 1));
        rm0 = fmaxf(rm0, __shfl_xor_sync(0xffffffffu, rm0, 2));
        rm1 = fmaxf(rm1, __shfl_xor_sync(0xffffffffu, rm1, 1));
        rm1 = fmaxf(rm1, __shfl_xor_sync(0xffffffffu, rm1, 2));
        const float mn0 = fmaxf(m0, rm0), mn1 = fmaxf(m1, rm1);
        const float c0 = __expf(m0 - mn0), c1 = __expf(m1 - mn1);
        float sum0 = 0.f, sum1 = 0.f;
#pragma unroll
        for (int jj = 0; jj < 8; jj++) {
            s[jj][0] = __expf(s[jj][0] - mn0); sum0 += s[jj][0];
            s[jj][1] = __expf(s[jj][1] - mn0); sum0 += s[jj][1];
            s[jj][2] = __expf(s[jj][2] - mn1); sum1 += s[jj][2];
            s[jj][3] = __expf(s[jj][3] - mn1); sum1 += s[jj][3];
        }
        sum0 += __shfl_xor_sync(0xffffffffu, sum0, 1);
        sum0 += __shfl_xor_sync(0xffffffffu, sum0, 2);
        sum1 += __shfl_xor_sync(0xffffffffu, sum1, 1);
        sum1 += __shfl_xor_sync(0xffffffffu, sum1, 2);
        l0 = l0 * c0 + sum0; m0 = mn0;
        l1 = l1 * c1 + sum1; m1 = mn1;
#pragma unroll
        for (int jj = 0; jj < 8; jj++) {
            o[jj][0] *= c0; o[jj][1] *= c0;
            o[jj][2] *= c1; o[jj][3] *= c1;
        }

        // ---- stage P (tf32), then PV ----
        {
            uint32_t* Pw = Ps + w * 16 * PS_W;
#pragma unroll
            for (int jj = 0; jj < 8; jj++) {
                uint2 hi0 = make_uint2(f2tf32(s[jj][0]), f2tf32(s[jj][1]));
                uint2 hi1 = make_uint2(f2tf32(s[jj][2]), f2tf32(s[jj][3]));
                *(uint2*)&Pw[g * PS_W + jj * 8 + 2 * tg] = hi0;
                *(uint2*)&Pw[(g + 8) * PS_W + jj * 8 + 2 * tg] = hi1;
            }
        }
        __syncwarp();
#pragma unroll
        for (int kb8 = 0; kb8 < 8; kb8++) {
            const int kc = kb8 * 8;
            uint32_t a[4];
            ldsm_x4(a[0], a[1], a[2], a[3],
                    pwBase + (pRow * PS_W + kc + pCol) * 4);
#pragma unroll
            for (int jj = 0; jj < 8; jj++) {
                const int n = jj * 8 + g;
                uint32_t bh[2];
                bh[0] = Vs[(kc + tg) * KS_W + n];
                bh[1] = Vs[(kc + tg + 4) * KS_W + n];
                mma_tf32(o[jj], a, bh);
            }
        }
        __syncthreads();   // all reads of Ks/Vs/Ps done before next tile
    }

    // ---- normalize + store ----
    const float inv0 = 1.f / l0, inv1 = 1.f / l1;
    float* op0 = out + ((size_t)b * NN + q0 + w * 16 + g) * DM + h * DH;
    float* op1 = op0 + (size_t)8 * DM;
#pragma unroll
    for (int jj = 0; jj < 8; jj++) {
        *(float2*)(op0 + jj * 8 + 2 * tg) = make_float2(o[jj][0] * inv0, o[jj][1] * inv0);
        *(float2*)(op1 + jj * 8 + 2 * tg) = make_float2(o[jj][2] * inv1, o[jj][3] * inv1);
    }
}

// ---------------------------------------------------------------------------
extern "C" void kernel_launch(void* const* d_in, const int* in_sizes, int n_in,
                              void* d_out, int out_size)
{
    const float* x     = (const float*)d_in[0];
    const float* bias  = (const float*)d_in[1];
    const float* Wqkv  = (const float*)d_in[2];
    const float* Wproj = (const float*)d_in[3];
    const float* beta  = (const float*)d_in[4];
    float* out = (float*)d_out;

    float *qkv_ptr, *att_ptr;
    cudaGetSymbolAddress((void**)&qkv_ptr, g_qkv);
    cudaGetSymbolAddress((void**)&att_ptr, g_att);

    static bool attr_set = false;
    if (!attr_set) {
        cudaFuncSetAttribute(flash_mma, cudaFuncAttributeMaxDynamicSharedMemorySize, FA2_SMEM);
        attr_set = true;
    }

    // 1) QKV projection (tf32 mma.sync, double-buffered, ldmatrix)
    gemm_mma<<<dim3(QKV_COLS / 128, M_ROWS / 128), 256>>>(x, Wqkv, qkv_ptr,
                                                          M_ROWS, QKV_COLS, DM);

    // 2) Tensorized flash attention (single-MMA PV)
    flash_mma<<<dim3(NN / 128, BB * HH), 256, FA2_SMEM>>>(qkv_ptr, bias, beta, att_ptr);

    // 3) Output projection (tf32 mma.sync)
    gemm_mma<<<dim3(DM / 128, M_ROWS / 128), 256>>>(att_ptr, Wproj, out,
                                                    M_ROWS, DM, DM);
}